// round 15
// baseline (speedup 1.0000x reference)
#include <cuda_runtime.h>

#define NJ 16384
#define JT 16
#define NB (NJ / JT)        // 1024 blocks
#define NT 256

#define A_PART (21 * 21 * 16384)
#define LD_OFF (2 * A_PART)
#define Z_OFF  (LD_OFF + 1)
#define Z_PART (21 * 16384)

__device__ float g_partial[NB];
__device__ unsigned int g_done;   // zero-init; last block resets each launch

struct f4 { float v[4]; };
__device__ __forceinline__ f4 ld4(const float* p) {
    float4 t = *(const float4*)p;
    f4 r; r.v[0] = t.x; r.v[1] = t.y; r.v[2] = t.z; r.v[3] = t.w; return r;
}
__device__ __forceinline__ void st4(float* p, const float* a) {
    *(float4*)p = make_float4(a[0], a[1], a[2], a[3]);
}

__global__ __launch_bounds__(NT, 6) void gp_main(
    const float* __restrict__ l00r, const float* __restrict__ l00i,
    const float* __restrict__ l01r, const float* __restrict__ l01i,
    const float* __restrict__ l02r, const float* __restrict__ l02i,
    const float* __restrict__ l11r, const float* __restrict__ l11i,
    const float* __restrict__ l12r, const float* __restrict__ l12i,
    const float* __restrict__ l22r, const float* __restrict__ l22i,
    const float* __restrict__ zre,  const float* __restrict__ zim,
    float* __restrict__ out)
{
    __shared__ __align__(16) float sm[388 * JT];
    __shared__ float sRed[11];
    __shared__ float sF[NT];
    __shared__ unsigned int sLast;

    float* sT1r  = sm;              // [16][JT] row t*4+k
    float* sT1i  = sm + 16 * JT;
    float* sIS1r = sm + 32 * JT;    // [4][JT]
    float* sIS1i = sm + 36 * JT;
    float* sAr   = sm + 40 * JT;    // [16][JT]
    float* sAi   = sm + 56 * JT;
    float* sT2r  = sm + 72 * JT;    // [20][JT]
    float* sT2i  = sm + 92 * JT;
    float* sIS2r = sm + 112 * JT;   // [JT]
    float* sIS2i = sm + 113 * JT;
    float* sZr   = sm + 114 * JT;   // [21][JT]
    float* sZi   = sm + 135 * JT;
    float* sM2pr = sm + 156 * JT;   // [4][JT]
    float* sM2pi = sm + 160 * JT;
    float* sDXpr = sm + 164 * JT;   // [4][JT]
    float* sDXpi = sm + 168 * JT;
    float* sDYr  = sm + 172 * JT;   // [4][JT]
    float* sDYi  = sm + 176 * JT;
    float* sDXr  = sm + 180 * JT;   // [JT]
    float* sDXi  = sm + 181 * JT;
    float* sS1pr = sm + 182 * JT;   // [16][JT]
    float* sS1pi = sm + 198 * JT;
    float* sWr   = sm + 214 * JT;   // [21][JT]
    float* sWi   = sm + 235 * JT;
    float* sUr   = sm + 256 * JT;   // [20][JT]
    float* sUi   = sm + 276 * JT;
    float* sDr   = sm + 296 * JT;   // [21][JT]
    float* sDi   = sm + 317 * JT;
    float* sLamR = sm + 338 * JT;   // [25][JT]: 0-15 l02(k-row), 16-19 l12, 20-23 l11, 24 l22
    float* sLamI = sm + 363 * JT;   // ends at 388

    const int flat = threadIdx.x;
    const int jj   = flat & (JT - 1);
    const int j    = blockIdx.x * JT + jj;

    // ================= PREFETCH =================
    // 1a operands stay in registers (consumed before first barrier)
    const int tk = flat >> 4;            // 0..15
    const int p1t = tk & 3, p1k = tk >> 2;
    const int i0g = p1k * 65536 + p1t * NJ + j;
    const float pbr = l00r[i0g], pbi = l00i[i0g];
    const float pcr = l01r[i0g], pci = l01i[i0g];

    // 1b/1.5 operands -> cooperative smem staging (no long-lived registers)
    for (int idx = flat; idx < 25 * JT; idx += NT) {
        const int r = idx >> 4, c = idx & (JT - 1);
        const int gj = blockIdx.x * JT + c;
        const float* srcR; const float* srcI; int off;
        if (r < 16)      { srcR = l02r; srcI = l02i; off = r * NJ + gj; }
        else if (r < 20) { srcR = l12r; srcI = l12i; off = (r - 16) * NJ + gj; }
        else if (r < 24) { srcR = l11r; srcI = l11i; off = (r - 20) * NJ + gj; }
        else             { srcR = l22r; srcI = l22i; off = gj; }
        sLamR[idx] = srcR[off];
        sLamI[idx] = srcI[off];
    }

    // z prefetch (consumed at the same point; short-lived regs)
    {
        const int zq0 = flat >> 4, zc0 = flat & (JT - 1);
        sZr[flat] = zre[zq0 * NJ + blockIdx.x * JT + zc0];
        sZi[flat] = zim[zq0 * NJ + blockIdx.x * JT + zc0];
        if (flat < 21 * JT - NT) {
            const int z1 = flat + NT;
            const int zq1 = z1 >> 4, zc1 = z1 & (JT - 1);
            sZr[flat + NT] = zre[zq1 * NJ + blockIdx.x * JT + zc1];
            sZi[flat + NT] = zim[zq1 * NJ + blockIdx.x * JT + zc1];
        }
    }

    // ================= Phase 1a: (t,k,j) — all 256 threads =================
    {
        float nrm = pbr * pbr + pbi * pbi;
        float rn = __fdividef(1.0f, nrm);
        float ar = pbr * rn, ai = -pbi * rn;      // 1/lam00
        float bn = pcr * pcr + pci * pci;
        const int row = (p1t * 4 + p1k) * JT + jj;
        sS1pr[row] = bn * ar;
        sS1pi[row] = bn * ai;
        sT1r[row] = pcr * ar - pci * ai;
        sT1i[row] = pcr * ai + pci * ar;
        sAr[row] = ar;
        sAi[row] = ai;
        float ld = 0.5f * __logf(nrm);
#pragma unroll
        for (int off = 16; off; off >>= 1)
            ld += __shfl_down_sync(0xffffffffu, ld, off);
        if ((flat & 31) == 0) sRed[flat >> 5] = ld;
    }
    __syncthreads();

    // ================= Phase 1b + 1.5 (warps 0-1, named barrier) =============
    if (flat < 4 * JT) {
        const int t = flat >> 4;         // 0..3
        float Br[5], Bi[5];
#pragma unroll
        for (int a = 0; a < 4; ++a) {
            Br[a] = sLamR[(a * 4 + t) * JT + jj];
            Bi[a] = sLamI[(a * 4 + t) * JT + jj];
        }
        Br[4] = sLamR[(16 + t) * JT + jj];
        Bi[4] = sLamI[(16 + t) * JT + jj];

        float S1r = sLamR[(20 + t) * JT + jj], S1i = sLamI[(20 + t) * JT + jj];
        float T1re[4], T1im[4];
#pragma unroll
        for (int k = 0; k < 4; ++k) {
            const int row = (t * 4 + k) * JT + jj;
            S1r -= sS1pr[row];
            S1i -= sS1pi[row];
            T1re[k] = sT1r[row];
            T1im[k] = sT1i[row];
        }
        float ns = S1r * S1r + S1i * S1i;
        float rs = __fdividef(1.0f, ns);
        float is1r = S1r * rs, is1i = -S1i * rs;
        sIS1r[t * JT + jj] = is1r;
        sIS1i[t * JT + jj] = is1i;
        float ld = 0.5f * __logf(ns);

        float Gr = -Br[4], Gi = -Bi[4];
#pragma unroll
        for (int a = 0; a < 4; ++a) {
            Gr += Br[a] * T1re[a] + Bi[a] * T1im[a];
            Gi += Bi[a] * T1re[a] - Br[a] * T1im[a];
        }
        {   // doty_t
            float dyr = 0.f, dyi = 0.f;
#pragma unroll
            for (int i1 = 0; i1 < 4; ++i1) {
                float zr = sZr[(i1 * 4 + t) * JT + jj], zi = sZi[(i1 * 4 + t) * JT + jj];
                dyr += T1re[i1] * zr + T1im[i1] * zi;
                dyi += T1re[i1] * zi - T1im[i1] * zr;
            }
            dyr -= sZr[(16 + t) * JT + jj];
            dyi -= sZi[(16 + t) * JT + jj];
            sDYr[t * JT + jj] = dyr;
            sDYi[t * JT + jj] = dyi;
        }
        float M2r = 0.f, M2i = 0.f, dxr = 0.f, dxi = 0.f;
#pragma unroll
        for (int i = 0; i < 5; ++i) {
            float t2r, t2i;
            if (i < 4) {
                float ur = T1re[i] * is1r - T1im[i] * is1i;
                float ui = T1re[i] * is1i + T1im[i] * is1r;
                float are = sAr[(t * 4 + i) * JT + jj];
                float aim = sAi[(t * 4 + i) * JT + jj];
                t2r = ur * Gr - ui * Gi + are * Br[i] - aim * Bi[i];
                t2i = ur * Gi + ui * Gr + are * Bi[i] + aim * Br[i];
            } else {
                float ur = -is1r, ui = is1i;
                float d4 = 2.0f * is1i;
                t2r = ur * Gr - ui * Gi - d4 * Bi[4];
                t2i = ur * Gi + ui * Gr + d4 * Br[4];
            }
            const int row = (i < 4) ? (i * 4 + t) : (16 + t);
            sT2r[row * JT + jj] = t2r;
            sT2i[row * JT + jj] = t2i;
            M2r += Br[i] * t2r + Bi[i] * t2i;
            M2i += Br[i] * t2i - Bi[i] * t2r;
            float zr = sZr[row * JT + jj], zi = sZi[row * JT + jj];
            dxr += t2r * zr + t2i * zi;
            dxi += t2r * zi - t2i * zr;
        }
        sM2pr[t * JT + jj] = M2r;  sM2pi[t * JT + jj] = M2i;
        sDXpr[t * JT + jj] = dxr;  sDXpi[t * JT + jj] = dxi;

#pragma unroll
        for (int off = 16; off; off >>= 1)
            ld += __shfl_down_sync(0xffffffffu, ld, off);
        if ((flat & 31) == 0) sRed[8 + (flat >> 5)] = ld;

        asm volatile("bar.sync 1, 64;" ::: "memory");

        if (flat < JT) {
            float M2ra = sM2pr[flat] + sM2pr[JT + flat] + sM2pr[2 * JT + flat] + sM2pr[3 * JT + flat];
            float M2ia = sM2pi[flat] + sM2pi[JT + flat] + sM2pi[2 * JT + flat] + sM2pi[3 * JT + flat];
            float S2r = sLamR[24 * JT + flat] - M2ra;
            float S2i = sLamI[24 * JT + flat] - M2ia;
            float ns2 = S2r * S2r + S2i * S2i;
            float rs2 = __fdividef(1.0f, ns2);
            sIS2r[flat] = S2r * rs2;
            sIS2i[flat] = -S2i * rs2;
            sDXr[flat] = sDXpr[flat] + sDXpr[JT + flat] + sDXpr[2 * JT + flat] + sDXpr[3 * JT + flat]
                       - sZr[20 * JT + flat];
            sDXi[flat] = sDXpi[flat] + sDXpi[JT + flat] + sDXpi[2 * JT + flat] + sDXpi[3 * JT + flat]
                       - sZi[20 * JT + flat];
            float ld2 = 0.5f * __logf(ns2);
#pragma unroll
            for (int off = 8; off; off >>= 1)
                ld2 += __shfl_down_sync(0x0000ffffu, ld2, off);
            if (flat == 0) sRed[10] = ld2;
        }
    }
    __syncthreads();

    if (flat == 0) {
        float s = 0.f;
#pragma unroll
        for (int i = 0; i < 11; ++i) s += sRed[i];
        g_partial[blockIdx.x] = s;
        __threadfence();
        unsigned int old = atomicAdd(&g_done, 1u);
        sLast = (old == NB - 1) ? 1u : 0u;
    }

    // ---- Phase 1.75: w, u, d into smem + zout; tasks (p, jj) ----
    for (int task = flat; task < 21 * JT; task += NT) {
        const int p  = task >> 4;
        const int c  = task & (JT - 1);
        const int tt = p & 3, i0 = p >> 2;
        const float is2r = sIS2r[c], is2i = sIS2i[c];
        float wr, wi, ur = 0.f, ui = 0.f, dr, di;
        if (p < 20) {
            float t2r = sT2r[p * JT + c], t2i = sT2i[p * JT + c];
            wr = t2r * is2r - t2i * is2i;
            wi = t2r * is2i + t2i * is2r;
            float s1r = sIS1r[tt * JT + c], s1i = sIS1i[tt * JT + c];
            if (i0 < 4) {
                float t1r = sT1r[(tt * 4 + i0) * JT + c];
                float t1i = sT1i[(tt * 4 + i0) * JT + c];
                ur = t1r * s1r - t1i * s1i;
                ui = t1r * s1i + t1i * s1r;
                dr = sAr[(tt * 4 + i0) * JT + c];
                di = sAi[(tt * 4 + i0) * JT + c];
            } else {
                ur = -s1r; ui = s1i;
                dr = 0.f;  di = 2.0f * s1i;
            }
            sUr[p * JT + c] = ur;
            sUi[p * JT + c] = ui;
        } else {
            wr = -is2r; wi = is2i;
            dr = 0.f;   di = 2.0f * is2i;
        }
        sWr[p * JT + c] = wr;
        sWi[p * JT + c] = wi;
        sDr[p * JT + c] = dr;
        sDi[p * JT + c] = di;

        float dxr = sDXr[c], dxi = sDXi[c];
        float dyr = sDYr[tt * JT + c], dyi = sDYi[tt * JT + c];
        float zpr = sZr[p * JT + c], zpi = sZi[p * JT + c];
        float za = wr * dxr - wi * dxi + ur * dyr - ui * dyi + dr * zpr - di * zpi;
        float zb = wr * dxi + wi * dxr + ur * dyi + ui * dyr + dr * zpi + di * zpr;
        const int gj = blockIdx.x * JT + c;
        out[Z_OFF + p * NJ + gj]          = za;
        out[Z_OFF + Z_PART + p * NJ + gj] = zb;
    }
    __syncthreads();

    // ---- Phase 2: 252 workers (qg, p, jq); scalar, 7 q rows × 4 j ----
    if (flat < 252) {
        const int qg  = flat / 84;           // 0..2
        const int rem = flat - qg * 84;
        const int p   = rem >> 2;            // 0..20
        const int jq  = rem & 3;
        const int jj4 = jq * 4;
        const int j0  = blockIdx.x * JT + jj4;
        const int tt  = p & 3;

        f4 wr = ld4(&sWr[p * JT + jj4]), wi = ld4(&sWi[p * JT + jj4]);
        f4 dr = ld4(&sDr[p * JT + jj4]), di = ld4(&sDi[p * JT + jj4]);
        f4 ur, ui;
        if (p < 20) { ur = ld4(&sUr[p * JT + jj4]); ui = ld4(&sUi[p * JT + jj4]); }

        const int rowbase = p * 21 * NJ + j0;
        const int q0 = qg * 7;
#pragma unroll
        for (int qq = 0; qq < 7; ++qq) {
            const int q = q0 + qq;
            float cr[4], ci[4];
            if (q < 20) {
                f4 xr = ld4(&sT2r[q * JT + jj4]), xi = ld4(&sT2i[q * JT + jj4]);
#pragma unroll
                for (int e = 0; e < 4; ++e) {
                    cr[e] = wr.v[e] * xr.v[e] + wi.v[e] * xi.v[e];
                    ci[e] = wi.v[e] * xr.v[e] - wr.v[e] * xi.v[e];
                }
                if (p < 20 && (((p ^ q) & 3) == 0)) {
                    const int i1 = q >> 2;
                    if (i1 < 4) {
                        f4 vr = ld4(&sT1r[(tt * 4 + i1) * JT + jj4]);
                        f4 vi = ld4(&sT1i[(tt * 4 + i1) * JT + jj4]);
#pragma unroll
                        for (int e = 0; e < 4; ++e) {
                            cr[e] += ur.v[e] * vr.v[e] + ui.v[e] * vi.v[e];
                            ci[e] += ui.v[e] * vr.v[e] - ur.v[e] * vi.v[e];
                        }
                    } else {
#pragma unroll
                        for (int e = 0; e < 4; ++e) { cr[e] -= ur.v[e]; ci[e] -= ui.v[e]; }
                    }
                }
            } else {
#pragma unroll
                for (int e = 0; e < 4; ++e) { cr[e] = -wr.v[e]; ci[e] = -wi.v[e]; }
            }
            if (p == q) {
#pragma unroll
                for (int e = 0; e < 4; ++e) { cr[e] += dr.v[e]; ci[e] += di.v[e]; }
            }
            st4(&out[rowbase + q * NJ], cr);
            st4(&out[A_PART + rowbase + q * NJ], ci);
        }
    }

    // ---- fused logdet finalize (last block) ----
    __syncthreads();
    if (sLast) {
        float s = 0.f;
#pragma unroll
        for (int i = 0; i < NB / NT; ++i) s += g_partial[flat + i * NT];
        sF[flat] = s;
        __syncthreads();
        for (int off = NT / 2; off; off >>= 1) {
            if (flat < off) sF[flat] += sF[flat + off];
            __syncthreads();
        }
        if (flat == 0) {
            out[LD_OFF] = sF[0];
            g_done = 0u;
        }
    }
}

extern "C" void kernel_launch(void* const* d_in, const int* in_sizes, int n_in,
                              void* d_out, int out_size) {
    const float* l00r = (const float*)d_in[0];
    const float* l00i = (const float*)d_in[1];
    const float* l01r = (const float*)d_in[2];
    const float* l01i = (const float*)d_in[3];
    const float* l02r = (const float*)d_in[4];
    const float* l02i = (const float*)d_in[5];
    const float* l11r = (const float*)d_in[6];
    const float* l11i = (const float*)d_in[7];
    const float* l12r = (const float*)d_in[8];
    const float* l12i = (const float*)d_in[9];
    const float* l22r = (const float*)d_in[10];
    const float* l22i = (const float*)d_in[11];
    const float* zre  = (const float*)d_in[12];
    const float* zim  = (const float*)d_in[13];
    float* out = (float*)d_out;

    gp_main<<<NB, NT>>>(l00r, l00i, l01r, l01i, l02r, l02i,
                        l11r, l11i, l12r, l12i, l22r, l22i,
                        zre, zim, out);
}

// round 16
// speedup vs baseline: 1.5806x; 1.5806x over previous
#include <cuda_runtime.h>

#define NJ 16384
#define JT 16
#define NB (NJ / JT)        // 1024 blocks
#define NT 128

#define A_PART (21 * 21 * 16384)
#define LD_OFF (2 * A_PART)
#define Z_OFF  (LD_OFF + 1)
#define Z_PART (21 * 16384)

__device__ float g_partial[NB];
__device__ unsigned int g_done;   // zero-init; last block resets each launch

struct f4 { float v[4]; };
__device__ __forceinline__ f4 ld4(const float* p) {
    float4 t = *(const float4*)p;
    f4 r; r.v[0] = t.x; r.v[1] = t.y; r.v[2] = t.z; r.v[3] = t.w; return r;
}
__device__ __forceinline__ void st4(float* p, const float* a) {
    *(float4*)p = make_float4(a[0], a[1], a[2], a[3]);
}

__global__ __launch_bounds__(NT, 8) void gp_main(
    const float* __restrict__ l00r, const float* __restrict__ l00i,
    const float* __restrict__ l01r, const float* __restrict__ l01i,
    const float* __restrict__ l02r, const float* __restrict__ l02i,
    const float* __restrict__ l11r, const float* __restrict__ l11i,
    const float* __restrict__ l12r, const float* __restrict__ l12i,
    const float* __restrict__ l22r, const float* __restrict__ l22i,
    const float* __restrict__ zre,  const float* __restrict__ zim,
    float* __restrict__ out)
{
    __shared__ __align__(16) float sm[338 * JT];
    __shared__ float sRed[7];
    __shared__ float sF[NT];
    __shared__ unsigned int sLast;

    float* sT1r  = sm;              // [16][JT] row t*4+k
    float* sT1i  = sm + 16 * JT;
    float* sIS1r = sm + 32 * JT;    // [4][JT]
    float* sIS1i = sm + 36 * JT;
    float* sAr   = sm + 40 * JT;    // [16][JT]
    float* sAi   = sm + 56 * JT;
    float* sT2r  = sm + 72 * JT;    // [20][JT]
    float* sT2i  = sm + 92 * JT;
    float* sIS2r = sm + 112 * JT;   // [JT]
    float* sIS2i = sm + 113 * JT;
    float* sZr   = sm + 114 * JT;   // [21][JT]
    float* sZi   = sm + 135 * JT;
    float* sM2pr = sm + 156 * JT;   // [4][JT]
    float* sM2pi = sm + 160 * JT;
    float* sDXpr = sm + 164 * JT;   // [4][JT]
    float* sDXpi = sm + 168 * JT;
    float* sDYr  = sm + 172 * JT;   // [4][JT]
    float* sDYi  = sm + 176 * JT;
    float* sDXr  = sm + 180 * JT;   // [JT]
    float* sDXi  = sm + 181 * JT;
    float* sS1pr = sm + 182 * JT;   // [16][JT]
    float* sS1pi = sm + 198 * JT;
    float* sWr   = sm + 214 * JT;   // [21][JT]
    float* sWi   = sm + 235 * JT;
    float* sUr   = sm + 256 * JT;   // [20][JT]
    float* sUi   = sm + 276 * JT;
    float* sDr   = sm + 296 * JT;   // [21][JT]
    float* sDi   = sm + 317 * JT;

    const int flat = threadIdx.x;
    const int jj   = flat & (JT - 1);
    const int j    = blockIdx.x * JT + jj;

    // ================= PREFETCH (one DRAM round trip) =================
    // phase-1a: each thread owns tk0 and tk0+8
    const int tk0 = flat >> 4;           // 0..7
    float pb0r, pb0i, pc0r, pc0i, pb1r, pb1i, pc1r, pc1i;
    {
        const int t0 = tk0 & 3, k0 = tk0 >> 2;
        const int g0 = k0 * 65536 + t0 * NJ + j;
        pb0r = l00r[g0]; pb0i = l00i[g0];
        pc0r = l01r[g0]; pc0i = l01i[g0];
        const int tk1 = tk0 + 8;
        const int t1 = tk1 & 3, k1 = tk1 >> 2;
        const int g1 = k1 * 65536 + t1 * NJ + j;
        pb1r = l00r[g1]; pb1i = l00i[g1];
        pc1r = l01r[g1]; pc1i = l01i[g1];
    }

    float pS1r = 0.f, pS1i = 0.f, pBr[5], pBi[5];
    if (flat < 4 * JT) {                 // warps 0-1
        const int t = flat >> 4;
        const int m = t * NJ + j;
        pS1r = l11r[m]; pS1i = l11i[m];
#pragma unroll
        for (int a = 0; a < 4; ++a) {
            const int ib = (a * 4 + t) * NJ + j;
            pBr[a] = l02r[ib]; pBi[a] = l02i[ib];
        }
        pBr[4] = l12r[m];
        pBi[4] = l12i[m];
    }
    float pS2r = 0.f, pS2i = 0.f;
    if (flat < JT) { pS2r = l22r[j]; pS2i = l22i[j]; }

    // z prefetch: 336 entries over 128 threads (3 chunks)
    float pzr[3], pzi[3];
#pragma unroll
    for (int c = 0; c < 3; ++c) {
        const int idx = flat + c * NT;
        if (idx < 21 * JT) {
            const int zq = idx >> 4, zc = idx & (JT - 1);
            pzr[c] = zre[zq * NJ + blockIdx.x * JT + zc];
            pzi[c] = zim[zq * NJ + blockIdx.x * JT + zc];
        }
    }

    // ================= Phase 1a: 2 (t,k,j) tasks per thread =================
    {
        float ld = 0.f;
#pragma unroll
        for (int s = 0; s < 2; ++s) {
            const int tk = tk0 + s * 8;
            const int t = tk & 3, k = tk >> 2;
            const float br = s ? pb1r : pb0r, bi = s ? pb1i : pb0i;
            const float cr = s ? pc1r : pc0r, ci = s ? pc1i : pc0i;
            float nrm = br * br + bi * bi;
            float rn = __fdividef(1.0f, nrm);
            float ar = br * rn, ai = -bi * rn;    // 1/lam00
            float bn = cr * cr + ci * ci;
            const int row = (t * 4 + k) * JT + jj;
            sS1pr[row] = bn * ar;
            sS1pi[row] = bn * ai;
            sT1r[row] = cr * ar - ci * ai;
            sT1i[row] = cr * ai + ci * ar;
            sAr[row] = ar;
            sAi[row] = ai;
            ld += 0.5f * __logf(nrm);
        }
#pragma unroll
        for (int off = 16; off; off >>= 1)
            ld += __shfl_down_sync(0xffffffffu, ld, off);
        if ((flat & 31) == 0) sRed[flat >> 5] = ld;
    }
#pragma unroll
    for (int c = 0; c < 3; ++c) {
        const int idx = flat + c * NT;
        if (idx < 21 * JT) { sZr[idx] = pzr[c]; sZi[idx] = pzi[c]; }
    }
    __syncthreads();

    // ================= Phase 1b + 1.5 (warps 0-1, named barrier) =============
    if (flat < 4 * JT) {
        const int t = flat >> 4;         // 0..3
        float S1r = pS1r, S1i = pS1i;
        float T1re[4], T1im[4];
#pragma unroll
        for (int k = 0; k < 4; ++k) {
            const int row = (t * 4 + k) * JT + jj;
            S1r -= sS1pr[row];
            S1i -= sS1pi[row];
            T1re[k] = sT1r[row];
            T1im[k] = sT1i[row];
        }
        float ns = S1r * S1r + S1i * S1i;
        float rs = __fdividef(1.0f, ns);
        float is1r = S1r * rs, is1i = -S1i * rs;
        sIS1r[t * JT + jj] = is1r;
        sIS1i[t * JT + jj] = is1i;
        float ld = 0.5f * __logf(ns);

        float Gr = -pBr[4], Gi = -pBi[4];
#pragma unroll
        for (int a = 0; a < 4; ++a) {
            Gr += pBr[a] * T1re[a] + pBi[a] * T1im[a];
            Gi += pBi[a] * T1re[a] - pBr[a] * T1im[a];
        }
        {   // doty_t
            float dyr = 0.f, dyi = 0.f;
#pragma unroll
            for (int i1 = 0; i1 < 4; ++i1) {
                float zr = sZr[(i1 * 4 + t) * JT + jj], zi = sZi[(i1 * 4 + t) * JT + jj];
                dyr += T1re[i1] * zr + T1im[i1] * zi;
                dyi += T1re[i1] * zi - T1im[i1] * zr;
            }
            dyr -= sZr[(16 + t) * JT + jj];
            dyi -= sZi[(16 + t) * JT + jj];
            sDYr[t * JT + jj] = dyr;
            sDYi[t * JT + jj] = dyi;
        }
        float M2r = 0.f, M2i = 0.f, dxr = 0.f, dxi = 0.f;
#pragma unroll
        for (int i = 0; i < 5; ++i) {
            float t2r, t2i;
            if (i < 4) {
                float ur = T1re[i] * is1r - T1im[i] * is1i;
                float ui = T1re[i] * is1i + T1im[i] * is1r;
                float are = sAr[(t * 4 + i) * JT + jj];
                float aim = sAi[(t * 4 + i) * JT + jj];
                t2r = ur * Gr - ui * Gi + are * pBr[i] - aim * pBi[i];
                t2i = ur * Gi + ui * Gr + are * pBi[i] + aim * pBr[i];
            } else {
                float ur = -is1r, ui = is1i;
                float d4 = 2.0f * is1i;
                t2r = ur * Gr - ui * Gi - d4 * pBi[4];
                t2i = ur * Gi + ui * Gr + d4 * pBr[4];
            }
            const int row = (i < 4) ? (i * 4 + t) : (16 + t);
            sT2r[row * JT + jj] = t2r;
            sT2i[row * JT + jj] = t2i;
            M2r += pBr[i] * t2r + pBi[i] * t2i;
            M2i += pBr[i] * t2i - pBi[i] * t2r;
            float zr = sZr[row * JT + jj], zi = sZi[row * JT + jj];
            dxr += t2r * zr + t2i * zi;
            dxi += t2r * zi - t2i * zr;
        }
        sM2pr[t * JT + jj] = M2r;  sM2pi[t * JT + jj] = M2i;
        sDXpr[t * JT + jj] = dxr;  sDXpi[t * JT + jj] = dxi;

#pragma unroll
        for (int off = 16; off; off >>= 1)
            ld += __shfl_down_sync(0xffffffffu, ld, off);
        if ((flat & 31) == 0) sRed[4 + (flat >> 5)] = ld;

        asm volatile("bar.sync 1, 64;" ::: "memory");

        if (flat < JT) {
            float M2ra = sM2pr[flat] + sM2pr[JT + flat] + sM2pr[2 * JT + flat] + sM2pr[3 * JT + flat];
            float M2ia = sM2pi[flat] + sM2pi[JT + flat] + sM2pi[2 * JT + flat] + sM2pi[3 * JT + flat];
            float S2r = pS2r - M2ra, S2i = pS2i - M2ia;
            float ns2 = S2r * S2r + S2i * S2i;
            float rs2 = __fdividef(1.0f, ns2);
            sIS2r[flat] = S2r * rs2;
            sIS2i[flat] = -S2i * rs2;
            sDXr[flat] = sDXpr[flat] + sDXpr[JT + flat] + sDXpr[2 * JT + flat] + sDXpr[3 * JT + flat]
                       - sZr[20 * JT + flat];
            sDXi[flat] = sDXpi[flat] + sDXpi[JT + flat] + sDXpi[2 * JT + flat] + sDXpi[3 * JT + flat]
                       - sZi[20 * JT + flat];
            float ld2 = 0.5f * __logf(ns2);
#pragma unroll
            for (int off = 8; off; off >>= 1)
                ld2 += __shfl_down_sync(0x0000ffffu, ld2, off);
            if (flat == 0) sRed[6] = ld2;
        }
    }
    __syncthreads();

    if (flat == 0) {
        float s = 0.f;
#pragma unroll
        for (int i = 0; i < 7; ++i) s += sRed[i];
        g_partial[blockIdx.x] = s;
        __threadfence();
        unsigned int old = atomicAdd(&g_done, 1u);
        sLast = (old == NB - 1) ? 1u : 0u;
    }

    // ---- Phase 1.75: w, u, d into smem + zout; 336 tasks over 128 threads ----
    for (int task = flat; task < 21 * JT; task += NT) {
        const int p  = task >> 4;
        const int c  = task & (JT - 1);
        const int tt = p & 3, i0 = p >> 2;
        const float is2r = sIS2r[c], is2i = sIS2i[c];
        float wr, wi, ur = 0.f, ui = 0.f, dr, di;
        if (p < 20) {
            float t2r = sT2r[p * JT + c], t2i = sT2i[p * JT + c];
            wr = t2r * is2r - t2i * is2i;
            wi = t2r * is2i + t2i * is2r;
            float s1r = sIS1r[tt * JT + c], s1i = sIS1i[tt * JT + c];
            if (i0 < 4) {
                float t1r = sT1r[(tt * 4 + i0) * JT + c];
                float t1i = sT1i[(tt * 4 + i0) * JT + c];
                ur = t1r * s1r - t1i * s1i;
                ui = t1r * s1i + t1i * s1r;
                dr = sAr[(tt * 4 + i0) * JT + c];
                di = sAi[(tt * 4 + i0) * JT + c];
            } else {
                ur = -s1r; ui = s1i;
                dr = 0.f;  di = 2.0f * s1i;
            }
            sUr[p * JT + c] = ur;
            sUi[p * JT + c] = ui;
        } else {
            wr = -is2r; wi = is2i;
            dr = 0.f;   di = 2.0f * is2i;
        }
        sWr[p * JT + c] = wr;
        sWi[p * JT + c] = wi;
        sDr[p * JT + c] = dr;
        sDi[p * JT + c] = di;

        float dxr = sDXr[c], dxi = sDXi[c];
        float dyr = sDYr[tt * JT + c], dyi = sDYi[tt * JT + c];
        float zpr = sZr[p * JT + c], zpi = sZi[p * JT + c];
        float za = wr * dxr - wi * dxi + ur * dyr - ui * dyi + dr * zpr - di * zpi;
        float zb = wr * dxi + wi * dxr + ur * dyi + ui * dyr + dr * zpi + di * zpr;
        const int gj = blockIdx.x * JT + c;
        out[Z_OFF + p * NJ + gj]          = za;
        out[Z_OFF + Z_PART + p * NJ + gj] = zb;
    }
    __syncthreads();

    // ---- Phase 2: 252 workers over 128 threads (2 sequential tasks) ----
#pragma unroll
    for (int base = 0; base < 2 * NT; base += NT) {
        const int wtask = flat + base;
        if (wtask < 252) {
            const int qg  = wtask / 84;          // 0..2
            const int rem = wtask - qg * 84;
            const int p   = rem >> 2;            // 0..20
            const int jq  = rem & 3;
            const int jj4 = jq * 4;
            const int j0  = blockIdx.x * JT + jj4;
            const int tt  = p & 3;

            f4 wr = ld4(&sWr[p * JT + jj4]), wi = ld4(&sWi[p * JT + jj4]);
            f4 dr = ld4(&sDr[p * JT + jj4]), di = ld4(&sDi[p * JT + jj4]);
            f4 ur, ui;
            if (p < 20) { ur = ld4(&sUr[p * JT + jj4]); ui = ld4(&sUi[p * JT + jj4]); }

            const int rowbase = p * 21 * NJ + j0;
            const int q0 = qg * 7;
#pragma unroll
            for (int qq = 0; qq < 7; ++qq) {
                const int q = q0 + qq;
                float cr[4], ci[4];
                if (q < 20) {
                    f4 xr = ld4(&sT2r[q * JT + jj4]), xi = ld4(&sT2i[q * JT + jj4]);
#pragma unroll
                    for (int e = 0; e < 4; ++e) {
                        cr[e] = wr.v[e] * xr.v[e] + wi.v[e] * xi.v[e];
                        ci[e] = wi.v[e] * xr.v[e] - wr.v[e] * xi.v[e];
                    }
                    if (p < 20 && (((p ^ q) & 3) == 0)) {
                        const int i1 = q >> 2;
                        if (i1 < 4) {
                            f4 vr = ld4(&sT1r[(tt * 4 + i1) * JT + jj4]);
                            f4 vi = ld4(&sT1i[(tt * 4 + i1) * JT + jj4]);
#pragma unroll
                            for (int e = 0; e < 4; ++e) {
                                cr[e] += ur.v[e] * vr.v[e] + ui.v[e] * vi.v[e];
                                ci[e] += ui.v[e] * vr.v[e] - ur.v[e] * vi.v[e];
                            }
                        } else {
#pragma unroll
                            for (int e = 0; e < 4; ++e) { cr[e] -= ur.v[e]; ci[e] -= ui.v[e]; }
                        }
                    }
                } else {
#pragma unroll
                    for (int e = 0; e < 4; ++e) { cr[e] = -wr.v[e]; ci[e] = -wi.v[e]; }
                }
                if (p == q) {
#pragma unroll
                    for (int e = 0; e < 4; ++e) { cr[e] += dr.v[e]; ci[e] += di.v[e]; }
                }
                st4(&out[rowbase + q * NJ], cr);
                st4(&out[A_PART + rowbase + q * NJ], ci);
            }
        }
    }

    // ---- fused logdet finalize (last block) ----
    __syncthreads();
    if (sLast) {
        float s = 0.f;
#pragma unroll
        for (int i = 0; i < NB / NT; ++i) s += g_partial[flat + i * NT];
        sF[flat] = s;
        __syncthreads();
        for (int off = NT / 2; off; off >>= 1) {
            if (flat < off) sF[flat] += sF[flat + off];
            __syncthreads();
        }
        if (flat == 0) {
            out[LD_OFF] = sF[0];
            g_done = 0u;
        }
    }
}

extern "C" void kernel_launch(void* const* d_in, const int* in_sizes, int n_in,
                              void* d_out, int out_size) {
    const float* l00r = (const float*)d_in[0];
    const float* l00i = (const float*)d_in[1];
    const float* l01r = (const float*)d_in[2];
    const float* l01i = (const float*)d_in[3];
    const float* l02r = (const float*)d_in[4];
    const float* l02i = (const float*)d_in[5];
    const float* l11r = (const float*)d_in[6];
    const float* l11i = (const float*)d_in[7];
    const float* l12r = (const float*)d_in[8];
    const float* l12i = (const float*)d_in[9];
    const float* l22r = (const float*)d_in[10];
    const float* l22i = (const float*)d_in[11];
    const float* zre  = (const float*)d_in[12];
    const float* zim  = (const float*)d_in[13];
    float* out = (float*)d_out;

    gp_main<<<NB, NT>>>(l00r, l00i, l01r, l01i, l02r, l02i,
                        l11r, l11i, l12r, l12i, l22r, l22i,
                        zre, zim, out);
}